// round 1
// baseline (speedup 1.0000x reference)
#include <cuda_runtime.h>

// Problem constants (fixed by the reference):
//   features [8192, 256], adj [8192, 8192], neigh_W [256, 256], lin_W [256, 512]
//   out [8192, 256] fp32
#define NN_NODES 8192
#define FF_DIM   256
#define OUT_DIM  256

// Scratch (no cudaMalloc allowed)
__device__ float g_h[NN_NODES * FF_DIM];       // features @ neigh_W^T
__device__ float g_agg[NN_NODES * FF_DIM];     // (adj @ h) / deg
__device__ float g_invdeg[NN_NODES];           // 1 / (rowsum(adj) + 1)

// ---------------------------------------------------------------------------
// Row-sum of adj -> 1/(sum+1). One block per row, 256 threads, float4 loads.
// ---------------------------------------------------------------------------
__global__ void rowsum_kernel(const float* __restrict__ adj) {
    const int row = blockIdx.x;
    const float4* a = reinterpret_cast<const float4*>(adj + (size_t)row * NN_NODES);
    float s = 0.0f;
    for (int i = threadIdx.x; i < NN_NODES / 4; i += 256) {
        float4 v = a[i];
        s += (v.x + v.y) + (v.z + v.w);
    }
    #pragma unroll
    for (int o = 16; o > 0; o >>= 1) s += __shfl_xor_sync(0xffffffffu, s, o);
    __shared__ float ws[8];
    const int w = threadIdx.x >> 5;
    if ((threadIdx.x & 31) == 0) ws[w] = s;
    __syncthreads();
    if (threadIdx.x == 0) {
        float t = 0.0f;
        #pragma unroll
        for (int i = 0; i < 8; i++) t += ws[i];
        g_invdeg[row] = 1.0f / (t + 1.0f);
    }
}

// ---------------------------------------------------------------------------
// Tiled SGEMM: C[M,N] = op(A,B) with
//   A row-major [M,K], lda
//   B_NT=true : B row-major [N,K] (ldb = row stride) -> C[m][n]=sum A[m][k]*B[n][k]
//   B_NT=false: B row-major [K,N] (ldb = row stride) -> C[m][n]=sum A[m][k]*B[k][n]
// Tile 128x128xBK8, 256 threads, 8x8 microtile per thread.
// Optional epilogue: scale row m by g_invdeg[m]; optional accumulate into C.
// All dims are multiples of the tile sizes in this problem -> no bounds checks.
// ---------------------------------------------------------------------------
template <bool B_NT, bool USE_INVDEG, bool ACCUM>
__global__ __launch_bounds__(256, 2)
void sgemm_kernel(const float* __restrict__ A, const float* __restrict__ B,
                  float* __restrict__ C,
                  int K, int lda, int ldb, int ldc)
{
    __shared__ float As[8][128];
    __shared__ float Bs[8][132];   // +4 pad

    const int tid = threadIdx.x;
    const int bm = blockIdx.y * 128;
    const int bn = blockIdx.x * 128;

    // A tile loader: row = tid/2 (0..127), k4 = (tid&1)*4
    const int a_row = tid >> 1;
    const int a_k   = (tid & 1) * 4;
    const float* Aptr = A + (size_t)(bm + a_row) * lda + a_k;

    // B tile loader
    const float* Bptr;
    int b_n, b_k;
    if (B_NT) {
        b_n = tid >> 1;          // 0..127 (tile col)
        b_k = (tid & 1) * 4;     // 0 or 4
        Bptr = B + (size_t)(bn + b_n) * ldb + b_k;
    } else {
        b_k = tid >> 5;          // 0..7
        b_n = (tid & 31) * 4;    // 0..124
        Bptr = B + (size_t)b_k * ldb + bn + b_n;
    }

    const int tx = tid & 15;     // output col group (8 cols each)
    const int ty = tid >> 4;     // output row group (8 rows each)

    float acc[8][8];
    #pragma unroll
    for (int i = 0; i < 8; i++)
        #pragma unroll
        for (int j = 0; j < 8; j++) acc[i][j] = 0.0f;

    for (int k0 = 0; k0 < K; k0 += 8) {
        // ---- global -> shared ----
        float4 av = *reinterpret_cast<const float4*>(Aptr);
        As[a_k + 0][a_row] = av.x;
        As[a_k + 1][a_row] = av.y;
        As[a_k + 2][a_row] = av.z;
        As[a_k + 3][a_row] = av.w;
        Aptr += 8;

        float4 bv = *reinterpret_cast<const float4*>(Bptr);
        if (B_NT) {
            Bs[b_k + 0][b_n] = bv.x;
            Bs[b_k + 1][b_n] = bv.y;
            Bs[b_k + 2][b_n] = bv.z;
            Bs[b_k + 3][b_n] = bv.w;
            Bptr += 8;
        } else {
            *reinterpret_cast<float4*>(&Bs[b_k][b_n]) = bv;
            Bptr += (size_t)8 * ldb;
        }
        __syncthreads();

        // ---- compute ----
        #pragma unroll
        for (int kk = 0; kk < 8; kk++) {
            float a[8], b[8];
            float4 a0 = *reinterpret_cast<const float4*>(&As[kk][ty * 8]);
            float4 a1 = *reinterpret_cast<const float4*>(&As[kk][ty * 8 + 4]);
            a[0]=a0.x; a[1]=a0.y; a[2]=a0.z; a[3]=a0.w;
            a[4]=a1.x; a[5]=a1.y; a[6]=a1.z; a[7]=a1.w;
            float4 b0 = *reinterpret_cast<const float4*>(&Bs[kk][tx * 8]);
            float4 b1 = *reinterpret_cast<const float4*>(&Bs[kk][tx * 8 + 4]);
            b[0]=b0.x; b[1]=b0.y; b[2]=b0.z; b[3]=b0.w;
            b[4]=b1.x; b[5]=b1.y; b[6]=b1.z; b[7]=b1.w;
            #pragma unroll
            for (int i = 0; i < 8; i++)
                #pragma unroll
                for (int j = 0; j < 8; j++)
                    acc[i][j] = fmaf(a[i], b[j], acc[i][j]);
        }
        __syncthreads();
    }

    // ---- epilogue ----
    #pragma unroll
    for (int i = 0; i < 8; i++) {
        const int m = bm + ty * 8 + i;
        float scale = 1.0f;
        if (USE_INVDEG) scale = g_invdeg[m];
        float* crow = C + (size_t)m * ldc + bn + tx * 8;
        #pragma unroll
        for (int j = 0; j < 8; j += 4) {
            float4 v;
            v.x = acc[i][j + 0] * scale;
            v.y = acc[i][j + 1] * scale;
            v.z = acc[i][j + 2] * scale;
            v.w = acc[i][j + 3] * scale;
            if (ACCUM) {
                float4 o = *reinterpret_cast<const float4*>(&crow[j]);
                v.x += o.x; v.y += o.y; v.z += o.z; v.w += o.w;
            }
            *reinterpret_cast<float4*>(&crow[j]) = v;
        }
    }
}

// ---------------------------------------------------------------------------
extern "C" void kernel_launch(void* const* d_in, const int* in_sizes, int n_in,
                              void* d_out, int out_size)
{
    const float* features = (const float*)d_in[0];  // [8192, 256]
    const float* adj      = (const float*)d_in[1];  // [8192, 8192]
    const float* neigh_W  = (const float*)d_in[2];  // [256, 256]
    const float* lin_W    = (const float*)d_in[3];  // [256, 512]
    float* out = (float*)d_out;                     // [8192, 256]

    float* h      = nullptr;
    float* agg    = nullptr;
    cudaGetSymbolAddress((void**)&h,   g_h);
    cudaGetSymbolAddress((void**)&agg, g_agg);

    const dim3 blk(256);
    const dim3 grid_full(OUT_DIM / 128, NN_NODES / 128);  // (2, 64)

    // 1) inv-degree (independent of 2)
    rowsum_kernel<<<NN_NODES, blk>>>(adj);

    // 2) h = features @ neigh_W^T   (NT, K=256)
    sgemm_kernel<true, false, false><<<grid_full, blk>>>(
        features, neigh_W, h, FF_DIM, FF_DIM, FF_DIM, FF_DIM);

    // 3) agg = (adj @ h) * invdeg   (NN, K=8192) -- the big one
    sgemm_kernel<false, true, false><<<grid_full, blk>>>(
        adj, h, agg, NN_NODES, NN_NODES, FF_DIM, FF_DIM);

    // 4) out = features @ lin_W[:, :256]^T     (NT, K=256, ldb=512)
    sgemm_kernel<true, false, false><<<grid_full, blk>>>(
        features, lin_W, out, FF_DIM, FF_DIM, 2 * FF_DIM, OUT_DIM);

    // 5) out += agg @ lin_W[:, 256:]^T         (NT, K=256, ldb=512)
    sgemm_kernel<true, false, true><<<grid_full, blk>>>(
        agg, lin_W + FF_DIM, out, FF_DIM, FF_DIM, 2 * FF_DIM, OUT_DIM);
}

// round 2
// speedup vs baseline: 4.2377x; 4.2377x over previous
#include <cuda_runtime.h>
#include <cstdint>

#define NN_NODES 8192
#define FF_DIM   256
#define OUT_DIM  256

// Scratch (no cudaMalloc allowed)
__device__ float g_h[NN_NODES * FF_DIM];       // features @ neigh_W^T
__device__ float g_agg[NN_NODES * FF_DIM];     // (adj @ h) / deg
__device__ float g_invdeg[NN_NODES];           // 1 / (rowsum(adj) + 1)

// ---------------------------------------------------------------------------
// helpers
// ---------------------------------------------------------------------------
__device__ __forceinline__ void cp_async16(uint32_t s, const void* g) {
    asm volatile("cp.async.ca.shared.global [%0], [%1], 16;\n" :: "r"(s), "l"(g));
}
__device__ __forceinline__ void cp_commit() { asm volatile("cp.async.commit_group;\n"); }
template <int N> __device__ __forceinline__ void cp_wait() {
    asm volatile("cp.async.wait_group %0;\n" :: "n"(N));
}
__device__ __forceinline__ uint32_t f2tf(float f) {
    uint32_t r;
    asm("cvt.rna.tf32.f32 %0, %1;\n" : "=r"(r) : "f"(f));
    return r;
}
__device__ __forceinline__ void mma_tf32(float* c, const uint32_t* a, const uint32_t* b) {
    asm volatile(
        "mma.sync.aligned.m16n8k8.row.col.f32.tf32.tf32.f32 "
        "{%0,%1,%2,%3}, {%4,%5,%6,%7}, {%8,%9}, {%0,%1,%2,%3};\n"
        : "+f"(c[0]), "+f"(c[1]), "+f"(c[2]), "+f"(c[3])
        : "r"(a[0]), "r"(a[1]), "r"(a[2]), "r"(a[3]), "r"(b[0]), "r"(b[1]));
}

// ---------------------------------------------------------------------------
// Row-sum of adj -> 1/(sum+1). One block per row, 256 threads, float4 loads.
// ---------------------------------------------------------------------------
__global__ void rowsum_kernel(const float* __restrict__ adj) {
    const int row = blockIdx.x;
    const float4* a = reinterpret_cast<const float4*>(adj + (size_t)row * NN_NODES);
    float s = 0.0f;
    for (int i = threadIdx.x; i < NN_NODES / 4; i += 256) {
        float4 v = a[i];
        s += (v.x + v.y) + (v.z + v.w);
    }
    #pragma unroll
    for (int o = 16; o > 0; o >>= 1) s += __shfl_xor_sync(0xffffffffu, s, o);
    __shared__ float ws[8];
    const int w = threadIdx.x >> 5;
    if ((threadIdx.x & 31) == 0) ws[w] = s;
    __syncthreads();
    if (threadIdx.x == 0) {
        float t = 0.0f;
        #pragma unroll
        for (int i = 0; i < 8; i++) t += ws[i];
        g_invdeg[row] = 1.0f / (t + 1.0f);
    }
}

// ---------------------------------------------------------------------------
// tf32 tensor-core GEMM, tile 128x128x32, 256 threads (8 warps, 64x32 warp tiles)
//   A row-major [M,K] (lda)
//   B_NT=true : B row-major [N,K] (ldb) -> C[m][n] = sum_k A[m][k]*B[n][k]
//   B_NT=false: B row-major [K,N] (ldb) -> C[m][n] = sum_k A[m][k]*B[k][n]
// Shared layouts:
//   As  [128][36]  m-major, pad 4   -> frag LDS bank = lane (conflict-free)
//   BsNT[128][36]  n-major, pad 4   -> same
//   BsNN[ 32][136] k-major, pad 8   -> frag LDS bank = 8*(lane%4)+lane/4 (c-free)
// cp.async double buffered. Epilogue: optional row-scale by g_invdeg, optional +=.
// All dims are multiples of tile sizes for this problem: no bounds checks.
// ---------------------------------------------------------------------------
#define STAGE_FLTS 9216          // 4608 (A) + 4608 (B, max of both layouts)
#define SMEM_BYTES (2 * STAGE_FLTS * 4)

template <bool B_NT, bool USE_INVDEG, bool ACCUM>
__global__ __launch_bounds__(256)
void tgemm(const float* __restrict__ A, const float* __restrict__ B,
           float* __restrict__ C, int K, int lda, int ldb, int ldc)
{
    extern __shared__ float sm[];
    const int tid  = threadIdx.x;
    const int lane = tid & 31;
    const int wid  = tid >> 5;
    const int wm   = wid & 1;     // warp row   (2 x 64 rows)
    const int wn   = wid >> 1;    // warp col   (4 x 32 cols)
    const int bm   = blockIdx.y * 128;
    const int bn   = blockIdx.x * 128;

    const uint32_t smem_base = (uint32_t)__cvta_generic_to_shared(sm);

    float acc[4][4][4];
    #pragma unroll
    for (int i = 0; i < 4; i++)
        #pragma unroll
        for (int j = 0; j < 4; j++)
            #pragma unroll
            for (int r = 0; r < 4; r++) acc[i][j][r] = 0.0f;

    // loader indices
    const int a_r  = tid >> 3;          // 0..31
    const int a_kv = (tid & 7) * 4;     // 0,4,...,28
    const int bnn_k = tid >> 5;         // 0..7
    const int bnn_n = (tid & 31) * 4;   // 0..124

    auto load_stage = [&](int t, int s) {
        const int k0 = t * 32;
        const uint32_t As = smem_base + (uint32_t)s * STAGE_FLTS * 4;
        const uint32_t Bs = As + 4608u * 4;
        #pragma unroll
        for (int p = 0; p < 4; p++) {
            const int r = a_r + 32 * p;
            cp_async16(As + (r * 36 + a_kv) * 4,
                       A + (size_t)(bm + r) * lda + k0 + a_kv);
        }
        if (B_NT) {
            #pragma unroll
            for (int p = 0; p < 4; p++) {
                const int n = a_r + 32 * p;
                cp_async16(Bs + (n * 36 + a_kv) * 4,
                           B + (size_t)(bn + n) * ldb + k0 + a_kv);
            }
        } else {
            #pragma unroll
            for (int p = 0; p < 4; p++) {
                const int k = bnn_k + 8 * p;
                cp_async16(Bs + (k * 136 + bnn_n) * 4,
                           B + (size_t)(k0 + k) * ldb + bn + bnn_n);
            }
        }
        cp_commit();
    };

    auto compute_stage = [&](int s) {
        const float* As = sm + s * STAGE_FLTS;
        const float* Bs = As + 4608;
        #pragma unroll
        for (int k8 = 0; k8 < 32; k8 += 8) {
            uint32_t af[4][4];
            #pragma unroll
            for (int mi = 0; mi < 4; mi++) {
                const int rm = wm * 64 + mi * 16 + (lane >> 2);
                const float* p = As + rm * 36 + k8 + (lane & 3);
                af[mi][0] = f2tf(p[0]);
                af[mi][1] = f2tf(p[8 * 36]);
                af[mi][2] = f2tf(p[4]);
                af[mi][3] = f2tf(p[8 * 36 + 4]);
            }
            uint32_t bf[4][2];
            #pragma unroll
            for (int ni = 0; ni < 4; ni++) {
                const int nb = wn * 32 + ni * 8 + (lane >> 2);
                if (B_NT) {
                    const float* p = Bs + nb * 36 + k8 + (lane & 3);
                    bf[ni][0] = f2tf(p[0]);
                    bf[ni][1] = f2tf(p[4]);
                } else {
                    const float* p = Bs + (k8 + (lane & 3)) * 136 + nb;
                    bf[ni][0] = f2tf(p[0]);
                    bf[ni][1] = f2tf(p[4 * 136]);
                }
            }
            #pragma unroll
            for (int mi = 0; mi < 4; mi++)
                #pragma unroll
                for (int ni = 0; ni < 4; ni++)
                    mma_tf32(acc[mi][ni], af[mi], bf[ni]);
        }
    };

    const int tiles = K >> 5;
    load_stage(0, 0);
    for (int t = 0; t < tiles; t++) {
        if (t + 1 < tiles) {
            load_stage(t + 1, (t + 1) & 1);
            cp_wait<1>();
        } else {
            cp_wait<0>();
        }
        __syncthreads();
        compute_stage(t & 1);
        __syncthreads();
    }

    // epilogue
    #pragma unroll
    for (int mi = 0; mi < 4; mi++) {
        const int r0 = bm + wm * 64 + mi * 16 + (lane >> 2);
        float s0 = 1.0f, s1 = 1.0f;
        if (USE_INVDEG) { s0 = g_invdeg[r0]; s1 = g_invdeg[r0 + 8]; }
        #pragma unroll
        for (int ni = 0; ni < 4; ni++) {
            const int c0 = bn + wn * 32 + ni * 8 + 2 * (lane & 3);
            float* p0 = C + (size_t)r0 * ldc + c0;
            float* p1 = C + (size_t)(r0 + 8) * ldc + c0;
            float2 v0 = make_float2(acc[mi][ni][0] * s0, acc[mi][ni][1] * s0);
            float2 v1 = make_float2(acc[mi][ni][2] * s1, acc[mi][ni][3] * s1);
            if (ACCUM) {
                const float2 o0 = *reinterpret_cast<const float2*>(p0);
                const float2 o1 = *reinterpret_cast<const float2*>(p1);
                v0.x += o0.x; v0.y += o0.y;
                v1.x += o1.x; v1.y += o1.y;
            }
            *reinterpret_cast<float2*>(p0) = v0;
            *reinterpret_cast<float2*>(p1) = v1;
        }
    }
}

// ---------------------------------------------------------------------------
extern "C" void kernel_launch(void* const* d_in, const int* in_sizes, int n_in,
                              void* d_out, int out_size)
{
    const float* features = (const float*)d_in[0];  // [8192, 256]
    const float* adj      = (const float*)d_in[1];  // [8192, 8192]
    const float* neigh_W  = (const float*)d_in[2];  // [256, 256]
    const float* lin_W    = (const float*)d_in[3];  // [256, 512]
    float* out = (float*)d_out;                     // [8192, 256]

    float* h   = nullptr;
    float* agg = nullptr;
    cudaGetSymbolAddress((void**)&h,   g_h);
    cudaGetSymbolAddress((void**)&agg, g_agg);

    cudaFuncSetAttribute(tgemm<true,  false, false>,
                         cudaFuncAttributeMaxDynamicSharedMemorySize, SMEM_BYTES);
    cudaFuncSetAttribute(tgemm<false, true,  false>,
                         cudaFuncAttributeMaxDynamicSharedMemorySize, SMEM_BYTES);
    cudaFuncSetAttribute(tgemm<true,  false, true>,
                         cudaFuncAttributeMaxDynamicSharedMemorySize, SMEM_BYTES);

    const dim3 blk(256);
    const dim3 grid_full(OUT_DIM / 128, NN_NODES / 128);  // (2, 64)

    // 1) inv-degree
    rowsum_kernel<<<NN_NODES, blk>>>(adj);

    // 2) h = features @ neigh_W^T   (NT, K=256)
    tgemm<true, false, false><<<grid_full, blk, SMEM_BYTES>>>(
        features, neigh_W, h, FF_DIM, FF_DIM, FF_DIM, FF_DIM);

    // 3) agg = (adj @ h) * invdeg   (NN, K=8192) -- the big one
    tgemm<false, true, false><<<grid_full, blk, SMEM_BYTES>>>(
        adj, h, agg, NN_NODES, NN_NODES, FF_DIM, FF_DIM);

    // 4) out = features @ lin_W[:, :256]^T   (NT, K=256, ldb=512)
    tgemm<true, false, false><<<grid_full, blk, SMEM_BYTES>>>(
        features, lin_W, out, FF_DIM, FF_DIM, 2 * FF_DIM, OUT_DIM);

    // 5) out += agg @ lin_W[:, 256:]^T       (NT, K=256, ldb=512)
    tgemm<true, false, true><<<grid_full, blk, SMEM_BYTES>>>(
        agg, lin_W + FF_DIM, out, FF_DIM, FF_DIM, 2 * FF_DIM, OUT_DIM);
}

// round 4
// speedup vs baseline: 5.1168x; 1.2074x over previous
#include <cuda_runtime.h>
#include <cstdint>

#define N_NODES 8192
#define F_DIM   256

// Scratch (no cudaMalloc allowed)
__device__ float g_h[(size_t)N_NODES * F_DIM];    // features @ neigh_W^T (tf32-rounded)
__device__ float g_agg[(size_t)N_NODES * F_DIM];  // (adj @ h)/deg (tf32-rounded)

// ---------------------------------------------------------------------------
// helpers
// ---------------------------------------------------------------------------
__device__ __forceinline__ void cp_async16(uint32_t s, const void* g) {
    asm volatile("cp.async.cg.shared.global [%0], [%1], 16;\n" :: "r"(s), "l"(g));
}
__device__ __forceinline__ void cp_commit() { asm volatile("cp.async.commit_group;\n"); }
template <int N> __device__ __forceinline__ void cp_wait() {
    asm volatile("cp.async.wait_group %0;\n" :: "n"(N));
}
__device__ __forceinline__ float rna_tf32(float f) {
    uint32_t r;
    asm("cvt.rna.tf32.f32 %0, %1;\n" : "=r"(r) : "f"(f));
    return __uint_as_float(r);
}
// tf32 mma on raw fp32 bit patterns: HW consumes only the tf32 bits (truncation).
__device__ __forceinline__ void mma_tf32(float* c, const uint32_t* a, const uint32_t* b) {
    asm volatile(
        "mma.sync.aligned.m16n8k8.row.col.f32.tf32.tf32.f32 "
        "{%0,%1,%2,%3}, {%4,%5,%6,%7}, {%8,%9}, {%0,%1,%2,%3};\n"
        : "+f"(c[0]), "+f"(c[1]), "+f"(c[2]), "+f"(c[3])
        : "r"(a[0]), "r"(a[1]), "r"(a[2]), "r"(a[3]), "r"(b[0]), "r"(b[1]));
}

// ---------------------------------------------------------------------------
// tf32 tensor GEMM, tile 128x128x32, 256 threads (8 warps, 64x32 warp tiles).
//   A row-major [M,K] (lda)
//   B_NT=true : B row-major [N,K] (ldb) -> C[m][n] = sum_k A[m][k]*B[n][k]
//   B_NT=false: B row-major [K,N] (ldb) -> C[m][n] = sum_k A[m][k]*B[k][n]
//   ROWSUM   : fused deg: s_m = sum over full K of A[m][:]; C row scaled 1/(s+1)
//   CONCAT   : A k in [0,256) from A, [256,512) from A2 (both lda=256)
//   ROUND_OUT: round stored C values to tf32 (rna) so downstream GEMMs see
//              exactly-representable operands (kills B-side truncation error)
// Shared: As[128][36] m-major; B NT [128][36]; B NN [32][136]. 3-stage ring.
// All dims are exact multiples of tile sizes -> no bounds checks.
// ---------------------------------------------------------------------------
#define A_FLTS 4608              // 128*36
#define B_FLTS 4608              // max(128*36, 32*136)
#define STAGE_FLTS (A_FLTS + B_FLTS)
#define NSTAGE 3
#define SMEM_BYTES (NSTAGE * STAGE_FLTS * 4)   // 110592

template <bool B_NT, bool ROWSUM, bool CONCAT, bool ROUND_OUT>
__global__ __launch_bounds__(256)
void tgemm(const float* __restrict__ A, const float* __restrict__ A2,
           const float* __restrict__ B, float* __restrict__ C,
           int K, int lda, int ldb, int ldc)
{
    extern __shared__ float sm[];
    __shared__ float s_part[256];
    __shared__ float s_inv[128];

    const int tid  = threadIdx.x;
    const int lane = tid & 31;
    const int wid  = tid >> 5;
    const int wm   = wid & 1;     // warp row (2 x 64 rows)
    const int wn   = wid >> 1;    // warp col (4 x 32 cols)
    const int bm   = blockIdx.y * 128;
    const int bn   = blockIdx.x * 128;

    const uint32_t smem_base = (uint32_t)__cvta_generic_to_shared(sm);

    float acc[4][4][4];
    #pragma unroll
    for (int i = 0; i < 4; i++)
        #pragma unroll
        for (int j = 0; j < 4; j++)
            #pragma unroll
            for (int r = 0; r < 4; r++) acc[i][j][r] = 0.0f;

    // loader indices
    const int a_r   = tid >> 3;          // 0..31
    const int a_kv  = (tid & 7) * 4;     // 0,4,...,28
    const int bnn_k = tid >> 5;          // 0..7
    const int bnn_n = (tid & 31) * 4;    // 0..124

    auto fill = [&](int t) {
        const int k0 = t * 32;
        const int s  = t % NSTAGE;
        const uint32_t sA = smem_base + (uint32_t)(s * STAGE_FLTS) * 4u;
        const uint32_t sB = sA + A_FLTS * 4u;
        const float* Asrc = A;
        int ka = k0;
        if (CONCAT && k0 >= F_DIM) { Asrc = A2; ka = k0 - F_DIM; }
        #pragma unroll
        for (int p = 0; p < 4; p++) {
            const int r = a_r + 32 * p;
            cp_async16(sA + (uint32_t)(r * 36 + a_kv) * 4u,
                       Asrc + (size_t)(bm + r) * lda + ka + a_kv);
        }
        if (B_NT) {
            #pragma unroll
            for (int p = 0; p < 4; p++) {
                const int n = a_r + 32 * p;
                cp_async16(sB + (uint32_t)(n * 36 + a_kv) * 4u,
                           B + (size_t)(bn + n) * ldb + k0 + a_kv);
            }
        } else {
            #pragma unroll
            for (int p = 0; p < 4; p++) {
                const int k = bnn_k + 8 * p;
                cp_async16(sB + (uint32_t)(k * 136 + bnn_n) * 4u,
                           B + (size_t)(k0 + k) * ldb + bn + bnn_n);
            }
        }
    };

    float row_acc = 0.0f;
    const int T = K >> 5;

    fill(0); cp_commit();
    fill(1); cp_commit();

    for (int t = 0; t < T; t++) {
        cp_wait<1>();
        __syncthreads();

        const int s = t % NSTAGE;
        const uint32_t* As = (const uint32_t*)(sm + s * STAGE_FLTS);
        const uint32_t* Bs = As + A_FLTS;

        #pragma unroll
        for (int k8 = 0; k8 < 32; k8 += 8) {
            uint32_t af[4][4];
            #pragma unroll
            for (int mi = 0; mi < 4; mi++) {
                const int rm = wm * 64 + mi * 16 + (lane >> 2);
                const uint32_t* p = As + rm * 36 + k8 + (lane & 3);
                af[mi][0] = p[0];
                af[mi][1] = p[8 * 36];
                af[mi][2] = p[4];
                af[mi][3] = p[8 * 36 + 4];
            }
            uint32_t bf[4][2];
            #pragma unroll
            for (int ni = 0; ni < 4; ni++) {
                const int nb = wn * 32 + ni * 8 + (lane >> 2);
                if (B_NT) {
                    const uint32_t* p = Bs + nb * 36 + k8 + (lane & 3);
                    bf[ni][0] = p[0];
                    bf[ni][1] = p[4];
                } else {
                    const uint32_t* p = Bs + (k8 + (lane & 3)) * 136 + nb;
                    bf[ni][0] = p[0];
                    bf[ni][1] = p[4 * 136];
                }
            }
            #pragma unroll
            for (int mi = 0; mi < 4; mi++)
                #pragma unroll
                for (int ni = 0; ni < 4; ni++)
                    mma_tf32(acc[mi][ni], af[mi], bf[ni]);
        }

        if (ROWSUM) {
            // thread tid sums 16 k-values of row tid>>1 (rotated to spread banks)
            const float* Ar = sm + s * STAGE_FLTS + (tid >> 1) * 36 + (tid & 1) * 16;
            const int rot = (tid >> 1) & 3;
            float st = 0.0f;
            #pragma unroll
            for (int i = 0; i < 4; i++) {
                const float4 v = *(const float4*)(Ar + (((i + rot) & 3) * 4));
                st += (v.x + v.y) + (v.z + v.w);
            }
            row_acc += st;
        }
        __syncthreads();

        if (t + 2 < T) fill(t + 2);
        cp_commit();
    }

    if (ROWSUM) {
        s_part[tid] = row_acc;
        __syncthreads();
        if (tid < 128)
            s_inv[tid] = 1.0f / (s_part[2 * tid] + s_part[2 * tid + 1] + 1.0f);
        __syncthreads();
    }

    // epilogue
    #pragma unroll
    for (int mi = 0; mi < 4; mi++) {
        const int lr0 = wm * 64 + mi * 16 + (lane >> 2);
        const int r0  = bm + lr0;
        float s0 = 1.0f, s1 = 1.0f;
        if (ROWSUM) { s0 = s_inv[lr0]; s1 = s_inv[lr0 + 8]; }
        #pragma unroll
        for (int ni = 0; ni < 4; ni++) {
            const int c0 = bn + wn * 32 + ni * 8 + 2 * (lane & 3);
            float* p0 = C + (size_t)r0 * ldc + c0;
            float* p1 = C + (size_t)(r0 + 8) * ldc + c0;
            float2 v0 = make_float2(acc[mi][ni][0] * s0, acc[mi][ni][1] * s0);
            float2 v1 = make_float2(acc[mi][ni][2] * s1, acc[mi][ni][3] * s1);
            if (ROUND_OUT) {
                v0.x = rna_tf32(v0.x); v0.y = rna_tf32(v0.y);
                v1.x = rna_tf32(v1.x); v1.y = rna_tf32(v1.y);
            }
            *reinterpret_cast<float2*>(p0) = v0;
            *reinterpret_cast<float2*>(p1) = v1;
        }
    }
}

// ---------------------------------------------------------------------------
extern "C" void kernel_launch(void* const* d_in, const int* in_sizes, int n_in,
                              void* d_out, int out_size)
{
    const float* features = (const float*)d_in[0];  // [8192, 256]
    const float* adj      = (const float*)d_in[1];  // [8192, 8192]
    const float* neigh_W  = (const float*)d_in[2];  // [256, 256]
    const float* lin_W    = (const float*)d_in[3];  // [256, 512]
    float* out = (float*)d_out;                     // [8192, 256]

    float *h = nullptr, *agg = nullptr;
    cudaGetSymbolAddress((void**)&h,   g_h);
    cudaGetSymbolAddress((void**)&agg, g_agg);

    cudaFuncSetAttribute(tgemm<true,  false, false, true >,
                         cudaFuncAttributeMaxDynamicSharedMemorySize, SMEM_BYTES);
    cudaFuncSetAttribute(tgemm<false, true,  false, true >,
                         cudaFuncAttributeMaxDynamicSharedMemorySize, SMEM_BYTES);
    cudaFuncSetAttribute(tgemm<true,  false, true,  false>,
                         cudaFuncAttributeMaxDynamicSharedMemorySize, SMEM_BYTES);

    const dim3 blk(256);
    const dim3 grid(2, 64);   // N/128 x M/128 for all three GEMMs

    // 1) h = round_tf32(features @ neigh_W^T)          (NT, K=256)
    tgemm<true, false, false, true><<<grid, blk, SMEM_BYTES>>>(
        features, nullptr, neigh_W, h, F_DIM, F_DIM, F_DIM, F_DIM);

    // 2) agg = round_tf32((adj @ h) / (rowsum(adj)+1)) (NN, K=8192, rowsum fused)
    tgemm<false, true, false, true><<<grid, blk, SMEM_BYTES>>>(
        adj, nullptr, h, agg, N_NODES, N_NODES, F_DIM, F_DIM);

    // 3) out = [features | agg] @ lin_W^T              (NT concat, K=512)
    tgemm<true, false, true, false><<<grid, blk, SMEM_BYTES>>>(
        features, agg, lin_W, out, 2 * F_DIM, F_DIM, 2 * F_DIM, F_DIM);
}